// round 15
// baseline (speedup 1.0000x reference)
#include <cuda_runtime.h>
#include <cuda_fp16.h>

#define L_FIXED 2048
#define TILE    128
#define JT      64
#define NTP     136
#define MAXB    16
#define EPSF    1e-8f
#define THRH    2.60f                   // fp16 filter threshold (1.5^2 + margin)
#define NTHREADS 256

// ---- global accumulators (zero at load; finalize resets for graph replay) ----
__device__ double   g_clash = 0.0;
__device__ double   g_bn    = 0.0;
__device__ double   g_bd    = 0.0;
__device__ double   g_lin   = 0.0;
__device__ double   g_S[MAXB];
__device__ unsigned g_count = 0;

__device__ __forceinline__ float sqrt_apx(float x) {
    float r; asm("sqrt.approx.f32 %0, %1;" : "=f"(r) : "f"(x)); return r;
}
__device__ __forceinline__ float warp_sum(float v) {
    #pragma unroll
    for (int off = 16; off > 0; off >>= 1)
        v += __shfl_down_sync(0xffffffffu, v, off);
    return v;
}
__device__ __forceinline__ unsigned h2u(half2 h) {
    unsigned u; asm("mov.b32 %0, %1;" : "=r"(u) : "r"(*(unsigned*)&h)); return u;
}

// ============================================================
// grid = (136 tile-pairs, B, 2 j-halves), block = 256.
// 128 i-rows x 64 j-cols; 4 i-rows/thread, 8 j/thread (4 half2 k-iters).
// Filter runs in fp16x2 (native HSUB2/HFMA2, 2 pairs/instr); the
// vote-gated slow path recomputes EXACT fp32 d^2 from raw coords and
// applies mask + seq-sep. fp16 never touches the accumulated value.
// ============================================================
__global__ void __launch_bounds__(NTHREADS)
fused_violation_kernel(const float* __restrict__ pos,
                       const float* __restrict__ mask,
                       float* __restrict__ out, int B)
{
    const int p   = blockIdx.x;
    const int b   = blockIdx.y;
    const int zh  = blockIdx.z;
    const int tid = threadIdx.x;

    // closed-form triangular decode (exact at perfect squares)
    const int ti = (int)((33.0f - sqrtf(1089.0f - 8.0f * (float)p)) * 0.5f);
    const int tj = ti + (p - (ti * (33 - ti)) / 2);
    const int i0 = ti * TILE;
    const int j0 = tj * TILE + zh * JT;

    const float* P = pos  + (size_t)b * L_FIXED * 3;
    const float* M = mask + (size_t)b * L_FIXED;

    // ---- stage j sub-tile: fp16 coords (packed as half2 pairs) +
    //      raw fp32 coords + mask for the exact slow path ----
    __shared__ __half shx[JT], shy[JT], shz[JT];
    __shared__ float  sfx[JT], sfy[JT], sfz[JT], sfm[JT];
    if (tid < JT) {
        int j = j0 + tid;
        float X = P[3*j], Y = P[3*j+1], Z = P[3*j+2];
        shx[tid] = __float2half_rn(X);
        shy[tid] = __float2half_rn(Y);
        shz[tid] = __float2half_rn(Z);
        sfx[tid] = X; sfy[tid] = Y; sfz[tid] = Z;
        sfm[tid] = M[j];
    }

    // ---- per-thread i rows (4 consecutive): fp16 broadcast + fp32 raw ----
    const int q = tid & 31;
    const int s = tid >> 5;
    const int ibase = i0 + 4 * q;
    half2 xh[4], yh[4], zh4[4];
    float xi[4], yi[4], zi[4], mi[4];
    {
        const float4* P4 = (const float4*)(P + 3 * ibase);
        float4 v0 = P4[0], v1 = P4[1], v2 = P4[2];
        float c[12] = {v0.x, v0.y, v0.z, v0.w, v1.x, v1.y, v1.z, v1.w,
                       v2.x, v2.y, v2.z, v2.w};
        const float4 mv = *(const float4*)(M + ibase);
        float mm[4] = {mv.x, mv.y, mv.z, mv.w};
        #pragma unroll
        for (int r = 0; r < 4; r++) {
            xi[r] = c[3*r]; yi[r] = c[3*r+1]; zi[r] = c[3*r+2];
            mi[r] = mm[r];
            xh[r] = __half2half2(__float2half_rn(xi[r]));
            yh[r] = __half2half2(__float2half_rn(yi[r]));
            zh4[r] = __half2half2(__float2half_rn(zi[r]));
        }
    }
    __syncthreads();

    const half2 NEGT = __half2half2(__float2half_rn(-THRH));
    const int kb = s * 4;

    float acc = 0.0f;
    const half2* jx2 = (const half2*)shx;
    const half2* jy2 = (const half2*)shy;
    const half2* jz2 = (const half2*)shz;

    #pragma unroll
    for (int k = 0; k < 4; k++) {
        half2 nx = jx2[kb+k], ny = jy2[kb+k], nz = jz2[kb+k];

        half2 d0x = __hsub2(xh[0], nx), d0y = __hsub2(yh[0], ny), d0z = __hsub2(zh4[0], nz);
        half2 u0  = __hfma2(d0z, d0z, __hfma2(d0y, d0y, __hfma2(d0x, d0x, NEGT)));
        half2 d1x = __hsub2(xh[1], nx), d1y = __hsub2(yh[1], ny), d1z = __hsub2(zh4[1], nz);
        half2 u1  = __hfma2(d1z, d1z, __hfma2(d1y, d1y, __hfma2(d1x, d1x, NEGT)));
        half2 d2x = __hsub2(xh[2], nx), d2y = __hsub2(yh[2], ny), d2z = __hsub2(zh4[2], nz);
        half2 u2  = __hfma2(d2z, d2z, __hfma2(d2y, d2y, __hfma2(d2x, d2x, NEGT)));
        half2 d3x = __hsub2(xh[3], nx), d3y = __hsub2(yh[3], ny), d3z = __hsub2(zh4[3], nz);
        half2 u3  = __hfma2(d3z, d3z, __hfma2(d3y, d3y, __hfma2(d3x, d3x, NEGT)));

        unsigned orv = (h2u(u0) | h2u(u1)) | (h2u(u2) | h2u(u3));
        if (__any_sync(0xffffffffu, (orv & 0x80008000u) != 0u)) {
            // exact fp32 slow path (rare): recompute d^2, mask + seq-sep
            int jlo = 2 * (kb + k);               // local j index (even)
            #pragma unroll
            for (int h = 0; h < 2; h++) {
                int jl = jlo + h;
                float xj = sfx[jl], yj = sfy[jl], zj = sfz[jl], mj = sfm[jl];
                int jg = j0 + jl;
                #pragma unroll
                for (int r = 0; r < 4; r++) {
                    int i = ibase + r;
                    float dx = xi[r] - xj;
                    float dy = yi[r] - yj;
                    float dz = zi[r] - zj;
                    float d2 = dx*dx + dy*dy + dz*dz;
                    float v  = fmaxf(1.5f - sqrt_apx(d2 + EPSF), 0.0f);
                    if (jg - i <= 2) v = 0.0f;    // seq-sep (also kills j<=i)
                    acc += v * mi[r] * mj;
                }
            }
        }
    }

    // ---- block reduction of clash partial ----
    __shared__ float swr[NTHREADS / 32];
    acc = warp_sum(acc);
    if ((tid & 31) == 0) swr[tid >> 5] = acc;
    __syncthreads();
    if (tid == 0) {
        float t = 0.0f;
        #pragma unroll
        for (int w = 0; w < NTHREADS / 32; w++) t += swr[w];
        if (t != 0.0f) atomicAdd(&g_clash, (double)t);
    }

    // ---- diagonal stats once per (diagonal tile, batch): zh==0 only ----
    if (ti == tj && zh == 0) {
        float bn = 0.0f, bd = 0.0f, S = 0.0f, lin = 0.0f;
        if (tid < TILE) {
            int i = i0 + tid;
            float m = M[i];
            S = m; lin = m * m;
            if (i + 1 < L_FIXED) {
                float mj = M[i + 1];
                float dx = P[3*(i+1)]   - P[3*i];
                float dy = P[3*(i+1)+1] - P[3*i+1];
                float dz = P[3*(i+1)+2] - P[3*i+2];
                float d  = sqrtf(dx*dx + dy*dy + dz*dz + EPSF);
                float viol = fmaxf(fabsf(d - 3.8f) - 0.4f, 0.0f);
                float mm = m * mj;
                bd = mm; bn = viol * mm; lin += 2.0f * mm;
            }
            if (i + 2 < L_FIXED) lin += 2.0f * m * M[i + 2];
        }
        bn  = warp_sum(bn);
        bd  = warp_sum(bd);
        S   = warp_sum(S);
        lin = warp_sum(lin);
        __shared__ float sst[NTHREADS / 32][4];
        if ((tid & 31) == 0) {
            int w = tid >> 5;
            sst[w][0] = bn; sst[w][1] = bd; sst[w][2] = S; sst[w][3] = lin;
        }
        __syncthreads();
        if (tid == 0) {
            float tbn = 0, tbd = 0, tS = 0, tlin = 0;
            #pragma unroll
            for (int w = 0; w < NTHREADS / 32; w++) {
                tbn += sst[w][0]; tbd += sst[w][1];
                tS  += sst[w][2]; tlin += sst[w][3];
            }
            atomicAdd(&g_bn,  (double)tbn);
            atomicAdd(&g_bd,  (double)tbd);
            atomicAdd(&g_S[b], (double)tS);
            atomicAdd(&g_lin, (double)tlin);
        }
    }

    // ---- last-block finalize ----
    __threadfence();
    __shared__ bool is_last;
    if (tid == 0) {
        unsigned total = gridDim.x * gridDim.y * gridDim.z;
        is_last = (atomicAdd(&g_count, 1u) == total - 1u);
    }
    __syncthreads();
    if (is_last && tid == 0) {
        double pd = 0.0;
        #pragma unroll
        for (int bb = 0; bb < MAXB; bb++) {
            if (bb < B) { double Sb = *((volatile double*)&g_S[bb]); pd += Sb * Sb; }
        }
        pd -= *((volatile double*)&g_lin);
        double bn = *((volatile double*)&g_bn);
        double bd = *((volatile double*)&g_bd);
        double cl = *((volatile double*)&g_clash);
        double bond  = bn / (bd + 1e-8);
        double clash = 2.0 * cl / (pd + 1e-8);
        out[0] = (float)bond;
        out[1] = (float)clash;
        out[2] = (float)(bond + clash);
        g_clash = 0.0; g_bn = 0.0; g_bd = 0.0; g_lin = 0.0; g_count = 0u;
        #pragma unroll
        for (int bb = 0; bb < MAXB; bb++) g_S[bb] = 0.0;
    }
}

extern "C" void kernel_launch(void* const* d_in, const int* in_sizes, int n_in,
                              void* d_out, int out_size)
{
    const float* pos  = (const float*)d_in[0];
    const float* mask = (const float*)d_in[1];
    int B = in_sizes[1] / L_FIXED;
    if (B > MAXB) B = MAXB;

    dim3 grid(NTP, B, 2);
    fused_violation_kernel<<<grid, NTHREADS>>>(pos, mask, (float*)d_out, B);
}

// round 16
// speedup vs baseline: 1.1515x; 1.1515x over previous
#include <cuda_runtime.h>

#define L_FIXED 2048
#define TILE    128
#define JT      64                        // j sub-tile width
#define NT      16
#define NTP     136
#define MAXB    16
#define EPSF    1e-8f
#define CLASH2  2.25f
#define NTHREADS 256

typedef unsigned long long ull;

// ---- global accumulators (zero at load; finalize resets for graph replay) ----
__device__ double   g_clash = 0.0;
__device__ double   g_bn    = 0.0;
__device__ double   g_bd    = 0.0;
__device__ double   g_lin   = 0.0;
__device__ double   g_S[MAXB];
__device__ unsigned g_count = 0;

// ---- Blackwell packed f32x2 helpers ----
__device__ __forceinline__ ull pack2(float x) {
    ull r; asm("mov.b64 %0, {%1, %1};" : "=l"(r) : "f"(x)); return r;
}
__device__ __forceinline__ ull add2(ull a, ull b) {
    ull r; asm("add.rn.f32x2 %0, %1, %2;" : "=l"(r) : "l"(a), "l"(b)); return r;
}
__device__ __forceinline__ ull mul2(ull a, ull b) {
    ull r; asm("mul.rn.f32x2 %0, %1, %2;" : "=l"(r) : "l"(a), "l"(b)); return r;
}
__device__ __forceinline__ ull fma2(ull a, ull b, ull c) {
    ull r; asm("fma.rn.f32x2 %0, %1, %2, %3;" : "=l"(r) : "l"(a), "l"(b), "l"(c)); return r;
}
__device__ __forceinline__ void unpack2(ull v, float &lo, float &hi) {
    asm("mov.b64 {%0, %1}, %2;" : "=f"(lo), "=f"(hi) : "l"(v));
}
__device__ __forceinline__ float sqrt_apx(float x) {
    float r; asm("sqrt.approx.f32 %0, %1;" : "=f"(r) : "f"(x)); return r;
}
__device__ __forceinline__ float warp_sum(float v) {
    #pragma unroll
    for (int off = 16; off > 0; off >>= 1)
        v += __shfl_down_sync(0xffffffffu, v, off);
    return v;
}
__device__ __forceinline__ void displace(int i, float &X, float &Y, float &Z) {
    X = 3.0e7f + 16.0f * (float)i; Y = 0.0f; Z = 0.0f;
}

// ============================================================
// grid = (136 tile-pairs, B, 2 j-halves), block = 256, >=6 blocks/SM.
// Block: 128 i-rows x 64 j-cols. 4 i-rows/thread, 8 j-slices of
// 8 j's (4 packed). LDS software-pipelined across the 4 k-iters.
// ============================================================
__global__ void __launch_bounds__(NTHREADS, 6)
fused_violation_kernel(const float* __restrict__ pos,
                       const float* __restrict__ mask,
                       float* __restrict__ out, int B)
{
    const int p   = blockIdx.x;
    const int b   = blockIdx.y;
    const int zh  = blockIdx.z;
    const int tid = threadIdx.x;

    // closed-form triangular decode (exact at perfect squares)
    const int ti = (int)((33.0f - sqrtf(1089.0f - 8.0f * (float)p)) * 0.5f);
    const int tj = ti + (p - (ti * (33 - ti)) / 2);
    const int i0 = ti * TILE;
    const int j0 = tj * TILE + zh * JT;

    const float* P = pos  + (size_t)b * L_FIXED * 3;
    const float* M = mask + (size_t)b * L_FIXED;

    // ---- stage j sub-tile (negated, masked atoms displaced) ----
    __shared__ ull sjx[JT/2], sjy[JT/2], sjz[JT/2];
    if (tid < JT) {
        int j = j0 + tid;
        float mj = M[j];
        float X = P[3*j], Y = P[3*j+1], Z = P[3*j+2];
        if (mj == 0.0f) displace(j, X, Y, Z);
        ((float*)sjx)[tid] = -X;
        ((float*)sjy)[tid] = -Y;
        ((float*)sjz)[tid] = -Z;
    }

    // ---- per-thread i rows (4 consecutive) ----
    const int q = tid & 31;
    const int s = tid >> 5;               // 8 slices x 4 packed j
    const int ibase = i0 + 4 * q;
    ull xr[4], yr[4], zr[4];
    {
        const float4* P4 = (const float4*)(P + 3 * ibase);
        float4 v0 = P4[0], v1 = P4[1], v2 = P4[2];
        float c[12] = {v0.x, v0.y, v0.z, v0.w, v1.x, v1.y, v1.z, v1.w,
                       v2.x, v2.y, v2.z, v2.w};
        const float4 mv = *(const float4*)(M + ibase);
        float mm[4] = {mv.x, mv.y, mv.z, mv.w};
        #pragma unroll
        for (int r = 0; r < 4; r++) {
            int i = ibase + r;
            float X = c[3*r], Y = c[3*r+1], Z = c[3*r+2];
            if (mm[r] == 0.0f) displace(i, X, Y, Z);
            xr[r] = pack2(X); yr[r] = pack2(Y); zr[r] = pack2(Z);
        }
    }
    __syncthreads();

    float acc = 0.0f;
    const int kb = s * 4;
    const bool need_mask = (ti == tj) || (tj == ti + 1 && zh == 0);

    if (!need_mask) {
        // fast path: d2-only + vote-gated sqrt, LDS pipelined
        ull nx = sjx[kb], ny = sjy[kb], nz = sjz[kb];
        #pragma unroll
        for (int k = 0; k < 4; k++) {
            ull nx2, ny2, nz2;
            if (k < 3) { nx2 = sjx[kb+k+1]; ny2 = sjy[kb+k+1]; nz2 = sjz[kb+k+1]; }
            float lo[4], hi[4];
            #pragma unroll
            for (int r = 0; r < 4; r++) {
                ull dx = add2(xr[r], nx), dy = add2(yr[r], ny), dz = add2(zr[r], nz);
                ull d2 = fma2(dz, dz, fma2(dy, dy, mul2(dx, dx)));
                unpack2(d2, lo[r], hi[r]);
            }
            float mn = fminf(fminf(fminf(lo[0], hi[0]), fminf(lo[1], hi[1])),
                             fminf(fminf(lo[2], hi[2]), fminf(lo[3], hi[3])));
            if (__any_sync(0xffffffffu, mn < CLASH2)) {
                #pragma unroll
                for (int r = 0; r < 4; r++) {
                    acc += fmaxf(1.5f - sqrt_apx(lo[r] + EPSF), 0.0f);
                    acc += fmaxf(1.5f - sqrt_apx(hi[r] + EPSF), 0.0f);
                }
            }
            nx = nx2; ny = ny2; nz = nz2;
        }
    } else {
        // near-diagonal: branchless approx-sqrt + seq-sep masking
        const ull EPS2 = pack2(EPSF);
        ull nx = sjx[kb], ny = sjy[kb], nz = sjz[kb];
        #pragma unroll
        for (int k = 0; k < 4; k++) {
            ull nx2, ny2, nz2;
            if (k < 3) { nx2 = sjx[kb+k+1]; ny2 = sjy[kb+k+1]; nz2 = sjz[kb+k+1]; }
            int jlo = j0 + 2 * (kb + k), jhi = jlo + 1;
            #pragma unroll
            for (int r = 0; r < 4; r++) {
                int i = ibase + r;
                ull dx = add2(xr[r], nx), dy = add2(yr[r], ny), dz = add2(zr[r], nz);
                ull d2 = fma2(dz, dz, fma2(dy, dy, fma2(dx, dx, EPS2)));
                float lo, hi; unpack2(d2, lo, hi);
                float vl = fmaxf(1.5f - sqrt_apx(lo), 0.0f);
                float vh = fmaxf(1.5f - sqrt_apx(hi), 0.0f);
                if (jlo - i <= 2) vl = 0.0f;
                if (jhi - i <= 2) vh = 0.0f;
                acc += vl + vh;
            }
            nx = nx2; ny = ny2; nz = nz2;
        }
    }

    // ---- block reduction of clash partial ----
    __shared__ float swr[NTHREADS / 32];
    acc = warp_sum(acc);
    if ((tid & 31) == 0) swr[tid >> 5] = acc;
    __syncthreads();
    if (tid == 0) {
        float t = 0.0f;
        #pragma unroll
        for (int w = 0; w < NTHREADS / 32; w++) t += swr[w];
        if (t != 0.0f) atomicAdd(&g_clash, (double)t);
    }

    // ---- diagonal stats once per (tile-on-diagonal, batch): zh==0 only ----
    if (ti == tj && zh == 0) {
        float bn = 0.0f, bd = 0.0f, S = 0.0f, lin = 0.0f;
        if (tid < TILE) {
            int i = i0 + tid;
            float m = M[i];
            S = m; lin = m * m;
            if (i + 1 < L_FIXED) {
                float mj = M[i + 1];
                float dx = P[3*(i+1)]   - P[3*i];
                float dy = P[3*(i+1)+1] - P[3*i+1];
                float dz = P[3*(i+1)+2] - P[3*i+2];
                float d  = sqrtf(dx*dx + dy*dy + dz*dz + EPSF);
                float viol = fmaxf(fabsf(d - 3.8f) - 0.4f, 0.0f);
                float mm = m * mj;
                bd = mm; bn = viol * mm; lin += 2.0f * mm;
            }
            if (i + 2 < L_FIXED) lin += 2.0f * m * M[i + 2];
        }
        bn  = warp_sum(bn);
        bd  = warp_sum(bd);
        S   = warp_sum(S);
        lin = warp_sum(lin);
        __shared__ float sst[NTHREADS / 32][4];
        if ((tid & 31) == 0) {
            int w = tid >> 5;
            sst[w][0] = bn; sst[w][1] = bd; sst[w][2] = S; sst[w][3] = lin;
        }
        __syncthreads();
        if (tid == 0) {
            float tbn = 0, tbd = 0, tS = 0, tlin = 0;
            #pragma unroll
            for (int w = 0; w < NTHREADS / 32; w++) {
                tbn += sst[w][0]; tbd += sst[w][1];
                tS  += sst[w][2]; tlin += sst[w][3];
            }
            atomicAdd(&g_bn,  (double)tbn);
            atomicAdd(&g_bd,  (double)tbd);
            atomicAdd(&g_S[b], (double)tS);
            atomicAdd(&g_lin, (double)tlin);
        }
    }

    // ---- last-block finalize ----
    __threadfence();
    __shared__ bool is_last;
    if (tid == 0) {
        unsigned total = gridDim.x * gridDim.y * gridDim.z;
        is_last = (atomicAdd(&g_count, 1u) == total - 1u);
    }
    __syncthreads();
    if (is_last && tid == 0) {
        double pd = 0.0;
        #pragma unroll
        for (int bb = 0; bb < MAXB; bb++) {
            if (bb < B) { double Sb = *((volatile double*)&g_S[bb]); pd += Sb * Sb; }
        }
        pd -= *((volatile double*)&g_lin);
        double bn = *((volatile double*)&g_bn);
        double bd = *((volatile double*)&g_bd);
        double cl = *((volatile double*)&g_clash);
        double bond  = bn / (bd + 1e-8);
        double clash = 2.0 * cl / (pd + 1e-8);
        out[0] = (float)bond;
        out[1] = (float)clash;
        out[2] = (float)(bond + clash);
        g_clash = 0.0; g_bn = 0.0; g_bd = 0.0; g_lin = 0.0; g_count = 0u;
        #pragma unroll
        for (int bb = 0; bb < MAXB; bb++) g_S[bb] = 0.0;
    }
}

extern "C" void kernel_launch(void* const* d_in, const int* in_sizes, int n_in,
                              void* d_out, int out_size)
{
    const float* pos  = (const float*)d_in[0];
    const float* mask = (const float*)d_in[1];
    int B = in_sizes[1] / L_FIXED;
    if (B > MAXB) B = MAXB;

    dim3 grid(NTP, B, 2);
    fused_violation_kernel<<<grid, NTHREADS>>>(pos, mask, (float*)d_out, B);
}